// round 8
// baseline (speedup 1.0000x reference)
#include <cuda_runtime.h>
#include <cuda_bf16.h>

// CrossHeadOnlineHadamardHook: 32-point Walsh-Hadamard across heads.
// x: (T, 4096) fp32 rows, T = 16384. heads = 32, HEAD_DIM = 128.
//
// R7: smem phase-split to coarsen global read/write interleave.
//   Phase A: CTA streams 4 contiguous token rows (64KB) gmem -> smem
//            as one sequential read burst.
//   Phase B: per-(token, quad) register FWHT from/to smem
//            (LDS.128/STS.128, conflict-free).
//   Phase C: CTA streams 64KB smem -> gmem as one sequential write burst.
// Targets the 21% DRAM-idle cycles (hypothesis: R/W bus turnaround from
// fine-grained global read/write mixing).

#define NUM_HEADS 32
#define HEAD_DIM  128
#define HIDDEN    (NUM_HEADS * HEAD_DIM)        // 4096 floats per token
#define TOKENS_PER_CTA 4
#define THREADS 128
#define F4_PER_TOKEN (HIDDEN / 4)               // 1024 float4
#define F4_PER_CTA (TOKENS_PER_CTA * F4_PER_TOKEN)   // 4096 float4 = 64KB
#define COPY_ITERS (F4_PER_CTA / THREADS)       // 32
#define SMEM_BYTES (F4_PER_CTA * 16)            // 65536

__global__ __launch_bounds__(THREADS)
void had32_crosshead_smem_kernel(const float4* __restrict__ x,
                                 float4* __restrict__ out)
{
    extern __shared__ float4 smem4[];           // 4096 float4 (64KB)

    const size_t cta_base = (size_t)blockIdx.x * F4_PER_CTA;
    const int tid = threadIdx.x;

    // ---- Phase A: contiguous 64KB read burst, gmem -> smem ----
    const float4* __restrict__ gin = x + cta_base;
#pragma unroll
    for (int k = 0; k < COPY_ITERS; ++k) {
        smem4[k * THREADS + tid] = __ldcs(gin + k * THREADS + tid);
    }
    __syncthreads();

    // ---- Phase B: register FWHT per (token, quad) ----
    // warp w (0..3) owns token w; lanes take consecutive quads -> LDS.128
    // across a warp touches 512B of consecutive smem: conflict-free.
    {
        const int tt = tid >> 5;                // token within CTA
        const int q  = tid & 31;                // float4 index within head dim
        float4* __restrict__ tok = smem4 + tt * F4_PER_TOKEN + q;

        float4 v[NUM_HEADS];
#pragma unroll
        for (int h = 0; h < NUM_HEADS; ++h) {
            v[h] = tok[h * (HEAD_DIM / 4)];
        }

#pragma unroll
        for (int s = 1; s < NUM_HEADS; s <<= 1) {
#pragma unroll
            for (int i = 0; i < NUM_HEADS; ++i) {
                if ((i & s) == 0) {
                    float4 a = v[i];
                    float4 b = v[i + s];
                    v[i].x     = a.x + b.x;
                    v[i].y     = a.y + b.y;
                    v[i].z     = a.z + b.z;
                    v[i].w     = a.w + b.w;
                    v[i + s].x = a.x - b.x;
                    v[i + s].y = a.y - b.y;
                    v[i + s].z = a.z - b.z;
                    v[i + s].w = a.w - b.w;
                }
            }
        }

        const float scl = 0.17677669529663687f;  // 1/sqrt(32)
#pragma unroll
        for (int h = 0; h < NUM_HEADS; ++h) {
            float4 r;
            r.x = v[h].x * scl;
            r.y = v[h].y * scl;
            r.z = v[h].z * scl;
            r.w = v[h].w * scl;
            tok[h * (HEAD_DIM / 4)] = r;
        }
    }
    __syncthreads();

    // ---- Phase C: contiguous 64KB write burst, smem -> gmem ----
    float4* __restrict__ gout = out + cta_base;
#pragma unroll
    for (int k = 0; k < COPY_ITERS; ++k) {
        __stcs(gout + k * THREADS + tid, smem4[k * THREADS + tid]);
    }
}

extern "C" void kernel_launch(void* const* d_in, const int* in_sizes, int n_in,
                              void* d_out, int out_size)
{
    const float4* x = (const float4*)d_in[0];
    float4* out = (float4*)d_out;

    // Opt in to >48KB dynamic smem (host-side attribute, not a stream op;
    // idempotent and capture-safe).
    cudaFuncSetAttribute(had32_crosshead_smem_kernel,
                         cudaFuncAttributeMaxDynamicSharedMemorySize,
                         SMEM_BYTES);

    int n = in_sizes[0];                         // total fp32 elements
    int tokens = n / HIDDEN;                     // 16384
    int blocks = tokens / TOKENS_PER_CTA;        // 4096

    had32_crosshead_smem_kernel<<<blocks, THREADS, SMEM_BYTES>>>(x, out);
}